// round 14
// baseline (speedup 1.0000x reference)
#include <cuda_runtime.h>
#include <cuda_fp16.h>
#include <cstdint>
#include <stdint.h>
#include <math.h>

#define NN 2048
#define KK 14
#define CC 512
#define OO 512
#define EE 78
#define BN_EPS 1e-5f
#define MTOT (NN * KK)     // 28672

// ---------------- device scratch ----------------
__device__ float g_S1[CC];
__device__ float g_Q[CC];
__device__ __half g_Ah[(size_t)MTOT * CC];     // fp16 X    (28 MB)
__device__ __half g_Ag[(size_t)MTOT * CC];     // fp16 agg  (28 MB)
__device__ __half g_Bh[2ull * OO * CC];        // fp16 Wo(0), Wm(1)

__device__ __forceinline__ uint32_t h2u(__half2 h) { return *reinterpret_cast<uint32_t*>(&h); }

#define LDSM_X4(r, addr)                                                      \
    asm volatile("ldmatrix.sync.aligned.m8n8.x4.shared.b16 {%0,%1,%2,%3}, [%4];" \
                 : "=r"((r)[0]), "=r"((r)[1]), "=r"((r)[2]), "=r"((r)[3])     \
                 : "r"(addr))
#define MMA_F16(Cr, A0, A1, A2, A3, B0, B1)                                   \
    asm volatile("mma.sync.aligned.m16n8k16.row.col.f32.f16.f16.f32 "          \
                 "{%0,%1,%2,%3}, {%4,%5,%6,%7}, {%8,%9}, {%0,%1,%2,%3};\n"     \
                 : "+f"(Cr[0]), "+f"(Cr[1]), "+f"(Cr[2]), "+f"(Cr[3])          \
                 : "r"(A0), "r"(A1), "r"(A2), "r"(A3), "r"(B0), "r"(B1))

// ---------------- pack weights to fp16 (+ zero stats in block 0) ----------------
__global__ __launch_bounds__(256) void k_packw(const float* __restrict__ Wm,
                                               const float* __restrict__ Wo) {
    if (blockIdx.x == 0) {
        int t = threadIdx.x;
        g_S1[t] = 0.f; g_S1[t + 256] = 0.f;
        g_Q[t]  = 0.f; g_Q[t + 256]  = 0.f;
    }
    int i = blockIdx.x * 1024 + threadIdx.x;
#pragma unroll
    for (int r = 0; r < 4; r++, i += 256) {
        g_Bh[i]           = __float2half(Wo[i]);
        g_Bh[OO * CC + i] = __float2half(Wm[i]);
    }
}

// ---------------- BN statistics + fp16 pack: 2 channels/thread ----------------
__global__ __launch_bounds__(256) void k_stats(const float* __restrict__ x) {
    int t = threadIdx.x;          // channels 2t, 2t+1
    int n0 = blockIdx.x * 8;
    float s1ax = 0.f, qax = 0.f, s1ay = 0.f, qay = 0.f;
    for (int r = 0; r < 8; r++) {
        int n = n0 + r;
        const float2* p = (const float2*)(x + (size_t)n * (KK * CC)) + t;
        __half2* ah = (__half2*)(g_Ah + ((size_t)n * KK) * CC) + t;
        float2 g = p[13 * 256];
        ah[13 * 256] = __floats2half2_rn(g.x, g.y);
        float s1x = 0.f, s2x = 0.f, wsx = 0.f;
        float s1y = 0.f, s2y = 0.f, wsy = 0.f;
#pragma unroll
        for (int k = 0; k < 13; k++) {
            float2 v = p[k * 256];
            ah[k * 256] = __floats2half2_rn(v.x, v.y);
            float dx = fabsf(v.x - g.x);
            float dy = fabsf(v.y - g.y);
            s1x += dx; s2x += dx * dx; wsx += (float)(12 - 2 * k) * dx;
            s1y += dy; s2y += dy * dy; wsy += (float)(12 - 2 * k) * dy;
        }
        s1ax += wsx; qax += 13.f * s2x - s1x * s1x;
        s1ay += wsy; qay += 13.f * s2y - s1y * s1y;
    }
    atomicAdd(&g_S1[2 * t],     s1ax);
    atomicAdd(&g_S1[2 * t + 1], s1ay);
    atomicAdd(&g_Q[2 * t],      qax);
    atomicAdd(&g_Q[2 * t + 1],  qay);
}

// ---------------- adjacency + tensor-core aggregation: 256 thr, 2 ch/thread ----------------
__global__ __launch_bounds__(256, 5) void k_adjW(const float* __restrict__ adjin,
                                                 const int* __restrict__ ei,
                                                 const int* __restrict__ ej,
                                                 const float* __restrict__ gamma,
                                                 const float* __restrict__ beta,
                                                 const float* __restrict__ wdir) {
    int n = blockIdx.x;
    int t = threadIdx.x;
    int lane = t & 31, warp = t >> 5;   // 8 warps

    __shared__ char buf[13 * 512 * 4];   // phase1: sd[13][512] f32 ; phase2: Xs[512][24] f16
    __shared__ float red[8];
    __shared__ float s_cst;
    __shared__ float sp[13];
    __shared__ float W[14][14];
    __shared__ float rn[14];
    __shared__ __half Whi[16][24];
    __shared__ __half Wlo[16][24];

    float (*sd)[CC] = (float (*)[CC])buf;
    int c0 = 2 * t;

    // --- inline finalize for channels c0, c0+1 ---
    const float inv = 1.f / (float)((size_t)NN * EE);
    float2 s1v = *(const float2*)&g_S1[c0];
    float2 qv  = *(const float2*)&g_Q[c0];
    float2 gmv = *(const float2*)&gamma[c0];
    float2 btv = *(const float2*)&beta[c0];
    float2 wv  = *(const float2*)&wdir[c0];
    float mx = 15.f * s1v.x * inv, my = 15.f * s1v.y * inv;
    float vx = 225.f * qv.x * inv - mx * mx;
    float vy = 225.f * qv.y * inv - my * my;
    float u0 = gmv.x * rsqrtf(vx + BN_EPS) * wv.x;
    float u1 = gmv.y * rsqrtf(vy + BN_EPS) * wv.y;
    float part = (btv.x * wv.x - mx * u0) + (btv.y * wv.y - my * u1);
#pragma unroll
    for (int off = 16; off > 0; off >>= 1)
        part += __shfl_xor_sync(0xffffffffu, part, off);
    if (lane == 0) red[warp] = part;

    // load fp16 X pair-column (14 nodes, channels c0,c0+1)
    const __half2* ah = (const __half2*)(g_Ah + ((size_t)n * KK) * CC) + t;
    __half2 hv[14];
#pragma unroll
    for (int k = 0; k < 14; k++) hv[k] = ah[k * 256];
    {
        float gx = __half2float(hv[13].x);
        float gy = __half2float(hv[13].y);
#pragma unroll
        for (int k = 0; k < 13; k++) {
            float2 d;
            d.x = fabsf(__half2float(hv[k].x) - gx) * u0;
            d.y = fabsf(__half2float(hv[k].y) - gy) * u1;
            *(float2*)&sd[k][c0] = d;
        }
    }
    if (t < 196) W[t / 14][t % 14] = adjin[t];
    __syncthreads();

    if (t == 0) {
        float s = 0.f;
#pragma unroll
        for (int i = 0; i < 8; i++) s += red[i];
        s_cst = s;
    }
    // 8 warps reduce 13 rows (warp w: rows w, w+8)
    for (int row = warp; row < 13; row += 8) {
        float s = 0.f;
#pragma unroll
        for (int i = 0; i < 16; i++) s += sd[row][lane + 32 * i];
        s += __shfl_xor_sync(0xffffffffu, s, 16);
        s += __shfl_xor_sync(0xffffffffu, s, 8);
        s += __shfl_xor_sync(0xffffffffu, s, 4);
        s += __shfl_xor_sync(0xffffffffu, s, 2);
        s += __shfl_xor_sync(0xffffffffu, s, 1);
        if (lane == 0) sp[row] = s;
    }
    __syncthreads();   // sd dead after this

    // edges -> W ; stage X transposed (rows 2t, 2t+1): Xs[512][16+pad], 48B rows
    if (t < EE) {
        int i = ei[t], j = ej[t];
        float z = 15.f * (sp[i] - sp[j]) + s_cst;
        float a = 1.f / (1.f + expf(-4.f * z));
        W[i][j] = 2.f * a * adjin[i * 14 + j];
        W[j][i] = 2.f * (1.f - a) * adjin[j * 14 + i];
    }
    {
        char* row0 = buf + (size_t)c0 * 48;
        char* row1 = row0 + 48;
        uint4 a0, a1;
        a0.x = h2u(__halves2half2(hv[0].x,  hv[1].x));
        a0.y = h2u(__halves2half2(hv[2].x,  hv[3].x));
        a0.z = h2u(__halves2half2(hv[4].x,  hv[5].x));
        a0.w = h2u(__halves2half2(hv[6].x,  hv[7].x));
        a1.x = h2u(__halves2half2(hv[8].x,  hv[9].x));
        a1.y = h2u(__halves2half2(hv[10].x, hv[11].x));
        a1.z = h2u(__halves2half2(hv[12].x, hv[13].x));
        a1.w = 0u;
        *(uint4*)row0        = a0;
        *(uint4*)(row0 + 16) = a1;
        a0.x = h2u(__halves2half2(hv[0].y,  hv[1].y));
        a0.y = h2u(__halves2half2(hv[2].y,  hv[3].y));
        a0.z = h2u(__halves2half2(hv[4].y,  hv[5].y));
        a0.w = h2u(__halves2half2(hv[6].y,  hv[7].y));
        a1.x = h2u(__halves2half2(hv[8].y,  hv[9].y));
        a1.y = h2u(__halves2half2(hv[10].y, hv[11].y));
        a1.z = h2u(__halves2half2(hv[12].y, hv[13].y));
        a1.w = 0u;
        *(uint4*)row1        = a0;
        *(uint4*)(row1 + 16) = a1;
    }
    __syncthreads();

    if (t < 14) {
        float s = 0.f;
#pragma unroll
        for (int j = 0; j < 14; j++) s += fabsf(W[t][j]);
        rn[t] = 1.f / fmaxf(s, 1e-12f);
    }
    __syncthreads();

    {   // build fp16 digit pair of W*rn, zero-padded to 16x16 (t covers 256 exactly)
        int i = t >> 4, j = t & 15;
        float v = (i < 14 && j < 14) ? W[i][j] * rn[i] : 0.f;
        __half hi = __float2half(v);
        Whi[i][j] = hi;
        Wlo[i][j] = __float2half(v - __half2float(hi));
    }
    __syncthreads();

    // Phase 2: each warp computes agg cols [64w, 64w+64) in two 32-col groups
    {
        int lr = lane & 15, lh = lane >> 4;
        uint32_t xsb  = (uint32_t)__cvta_generic_to_shared(buf);
        uint32_t whib = (uint32_t)__cvta_generic_to_shared(&Whi[0][0]);
        uint32_t wlob = (uint32_t)__cvta_generic_to_shared(&Wlo[0][0]);
        uint32_t aw = (uint32_t)(lr * 48 + lh * 16);

        uint32_t ahi[4], alo[4];
        LDSM_X4(ahi, whib + aw);
        LDSM_X4(alo, wlob + aw);

        int gid = lane >> 2, tig = lane & 3;
        __half* ag = g_Ag + ((size_t)n * KK) * CC;

#pragma unroll
        for (int h = 0; h < 2; h++) {
            int colbase = warp * 64 + h * 32;
            uint32_t bx0 = xsb + (uint32_t)((colbase + lr) * 48 + lh * 16);
            uint32_t bx1 = bx0 + 16 * 48;
            uint32_t bf0[4], bf1[4];
            LDSM_X4(bf0, bx0);
            LDSM_X4(bf1, bx1);

            float acc[4][4];
#pragma unroll
            for (int q = 0; q < 4; q++)
#pragma unroll
                for (int i = 0; i < 4; i++) acc[q][i] = 0.f;

            MMA_F16(acc[0], ahi[0], ahi[1], ahi[2], ahi[3], bf0[0], bf0[2]);
            MMA_F16(acc[0], alo[0], alo[1], alo[2], alo[3], bf0[0], bf0[2]);
            MMA_F16(acc[1], ahi[0], ahi[1], ahi[2], ahi[3], bf0[1], bf0[3]);
            MMA_F16(acc[1], alo[0], alo[1], alo[2], alo[3], bf0[1], bf0[3]);
            MMA_F16(acc[2], ahi[0], ahi[1], ahi[2], ahi[3], bf1[0], bf1[2]);
            MMA_F16(acc[2], alo[0], alo[1], alo[2], alo[3], bf1[0], bf1[2]);
            MMA_F16(acc[3], ahi[0], ahi[1], ahi[2], ahi[3], bf1[1], bf1[3]);
            MMA_F16(acc[3], alo[0], alo[1], alo[2], alo[3], bf1[1], bf1[3]);

#pragma unroll
            for (int q = 0; q < 4; q++) {
                int col = colbase + q * 8 + tig * 2;
                *(__half2*)&ag[(size_t)gid * CC + col] = __floats2half2_rn(acc[q][0], acc[q][1]);
                if (gid + 8 < 14)
                    *(__half2*)&ag[(size_t)(gid + 8) * CC + col] = __floats2half2_rn(acc[q][2], acc[q][3]);
            }
        }
    }
}

// ---------------- fused dual fp16 GEMM (R9/R13 version, frozen at 91us) ----------------
#define S_AX 0
#define S_AG 8192
#define S_BO 16384
#define S_BM 32768
#define STG  49152
#define SMEM_G (2 * STG)   // 98304

__device__ __forceinline__ void cpa16(uint32_t dst, const void* src) {
    asm volatile("cp.async.cg.shared.global [%0], [%1], 16;" :: "r"(dst), "l"(src));
}

__device__ __forceinline__ void g_load_chunk(uint32_t sb, int stg, int t,
                                             int m0, int o0, int tid) {
    uint32_t base = sb + (uint32_t)stg * STG;
    const __half* Ax = g_Ah + (size_t)m0 * CC + t * 64;
    const __half* Ag = g_Ag + (size_t)m0 * CC + t * 64;
    const __half* Bo = g_Bh + t * 64;
    const __half* Bm = g_Bh + (size_t)OO * CC + t * 64;
#pragma unroll
    for (int i = 0; i < 2; i++) {
        int idx = tid + i * 256;
        int r = idx >> 3, c = idx & 7;
        uint32_t off = (uint32_t)r * 128 + (uint32_t)c * 16;
        uint32_t sw = off ^ ((off >> 3) & 0x70);
        cpa16(base + S_AX + sw, Ax + (size_t)r * CC + c * 8);
        cpa16(base + S_AG + sw, Ag + (size_t)r * CC + c * 8);
    }
#pragma unroll
    for (int i = 0; i < 4; i++) {
        int idx = tid + i * 256;
        int r = idx >> 3, c = idx & 7;
        uint32_t off = (uint32_t)r * 128 + (uint32_t)c * 16;
        uint32_t sw = off ^ ((off >> 3) & 0x70);
        cpa16(base + S_BO + sw, Bo + (size_t)(o0 + r) * CC + c * 8);
        cpa16(base + S_BM + sw, Bm + (size_t)(o0 + r) * CC + c * 8);
    }
}

__global__ __launch_bounds__(256, 2) void k_gemm(float* __restrict__ out) {
    extern __shared__ char smem[];
    uint32_t sb = (uint32_t)__cvta_generic_to_shared(smem);
    int tid = threadIdx.x;
    int w = tid >> 5, l = tid & 31;
    int wm = w & 1;
    int wn = w >> 1;
    int m0 = blockIdx.x * 64;
    int o0 = blockIdx.y * 128;
    int lr = l & 15, lh = l >> 4;

    float accO[2][4][4], accM[2][4][4];
#pragma unroll
    for (int mt = 0; mt < 2; mt++)
#pragma unroll
        for (int nt = 0; nt < 4; nt++)
#pragma unroll
            for (int i = 0; i < 4; i++) { accO[mt][nt][i] = 0.f; accM[mt][nt][i] = 0.f; }

    g_load_chunk(sb, 0, 0, m0, o0, tid);
    asm volatile("cp.async.commit_group;" ::: "memory");
    g_load_chunk(sb, 1, 1, m0, o0, tid);
    asm volatile("cp.async.commit_group;" ::: "memory");

    const int NCH = CC / 64;   // 8
    for (int t = 0; t < NCH; t++) {
        int b = t & 1;
        if (t < NCH - 1) asm volatile("cp.async.wait_group 1;" ::: "memory");
        else             asm volatile("cp.async.wait_group 0;" ::: "memory");
        __syncthreads();

        uint32_t base = sb + (uint32_t)b * STG;
#pragma unroll
        for (int ks = 0; ks < 4; ks++) {
            uint32_t arow = (uint32_t)(wm * 32 + lr) * 128 + (uint32_t)lh * 16 + ks * 32;
            uint32_t brow = (uint32_t)(wn * 32 + lr) * 128 + (uint32_t)lh * 16 + ks * 32;
            uint32_t a0 = arow ^ ((arow >> 3) & 0x70);
            uint32_t a1 = (arow + 16 * 128) ^ (((arow + 16 * 128) >> 3) & 0x70);
            uint32_t b0 = brow ^ ((brow >> 3) & 0x70);
            uint32_t b1 = (brow + 16 * 128) ^ (((brow + 16 * 128) >> 3) & 0x70);
            {
                uint32_t af[2][4], bf[2][4];
                LDSM_X4(af[0], base + S_AX + a0);
                LDSM_X4(af[1], base + S_AX + a1);
                LDSM_X4(bf[0], base + S_BO + b0);
                LDSM_X4(bf[1], base + S_BO + b1);
#pragma unroll
                for (int mt = 0; mt < 2; mt++)
#pragma unroll
                    for (int i = 0; i < 2; i++) {
                        MMA_F16(accO[mt][2 * i],     af[mt][0], af[mt][1], af[mt][2], af[mt][3], bf[i][0], bf[i][2]);
                        MMA_F16(accO[mt][2 * i + 1], af[mt][0], af[mt][1], af[mt][2], af[mt][3], bf[i][1], bf[i][3]);
                    }
            }
            {
                uint32_t af[2][4], bf[2][4];
                LDSM_X4(af[0], base + S_AG + a0);
                LDSM_X4(af[1], base + S_AG + a1);
                LDSM_X4(bf[0], base + S_BM + b0);
                LDSM_X4(bf[1], base + S_BM + b1);
#pragma unroll
                for (int mt = 0; mt < 2; mt++)
#pragma unroll
                    for (int i = 0; i < 2; i++) {
                        MMA_F16(accM[mt][2 * i],     af[mt][0], af[mt][1], af[mt][2], af[mt][3], bf[i][0], bf[i][2]);
                        MMA_F16(accM[mt][2 * i + 1], af[mt][0], af[mt][1], af[mt][2], af[mt][3], bf[i][1], bf[i][3]);
                    }
            }
        }
        __syncthreads();

        if (t + 2 < NCH) {
            g_load_chunk(sb, b, t + 2, m0, o0, tid);
            asm volatile("cp.async.commit_group;" ::: "memory");
        }
    }

    int gid = l >> 2, tig = l & 3;
#pragma unroll
    for (int mt = 0; mt < 2; mt++) {
#pragma unroll
        for (int nt = 0; nt < 4; nt++) {
            float* p0 = out + (size_t)(m0 + wm * 32 + mt * 16 + gid) * OO + o0 + wn * 32 + nt * 8 + tig * 2;
            float* p1 = p0 + 8 * OO;
            *(float2*)p0 = make_float2(fmaxf(accM[mt][nt][0], 0.f) + accO[mt][nt][0],
                                       fmaxf(accM[mt][nt][1], 0.f) + accO[mt][nt][1]);
            *(float2*)p1 = make_float2(fmaxf(accM[mt][nt][2], 0.f) + accO[mt][nt][2],
                                       fmaxf(accM[mt][nt][3], 0.f) + accO[mt][nt][3]);
        }
    }
}

// ---------------- launch ----------------
extern "C" void kernel_launch(void* const* d_in, const int* in_sizes, int n_in,
                              void* d_out, int out_size) {
    const float* x     = (const float*)d_in[0];
    const float* adj   = (const float*)d_in[1];
    const int*   ei    = (const int*)d_in[2];
    const int*   ej    = (const int*)d_in[3];
    const float* gamma = (const float*)d_in[4];
    const float* beta  = (const float*)d_in[5];
    const float* wdir  = (const float*)d_in[6];
    const float* Wm    = (const float*)d_in[7];
    const float* Wo    = (const float*)d_in[8];
    float* out = (float*)d_out;

    cudaFuncSetAttribute(k_gemm, cudaFuncAttributeMaxDynamicSharedMemorySize, SMEM_G);

    k_packw<<<(OO * CC) / 1024, 256>>>(Wm, Wo);
    k_stats<<<NN / 8, 256>>>(x);
    k_adjW<<<NN, 256>>>(adj, ei, ej, gamma, beta, wdir);

    dim3 grid(MTOT / 64, OO / 128);   // 448 x 4
    k_gemm<<<grid, 256, SMEM_G>>>(out);
}